// round 1
// baseline (speedup 1.0000x reference)
#include <cuda_runtime.h>
#include <mma.h>
#include <math.h>

using namespace nvcuda;

// Problem constants (fixed by reference setup_inputs)
#define Bb 8
#define Ss 2048
#define Dd 1024
#define NEGV -999999.0f

// GEMM tiling
#define BM 128
#define BN 128
#define BK 16

// Scratch: __device__ globals (no runtime allocation allowed)
__device__ float g_Q[(size_t)Bb * Ss * Dd];   // 64 MB
__device__ float g_K[(size_t)Bb * Ss * Dd];   // 64 MB
__device__ float g_V[(size_t)Bb * Ss * Dd];   // 64 MB
__device__ float g_P[(size_t)Bb * Ss * Ss];   // 128 MB (scores -> probs in place)

// ---------------------------------------------------------------------------
// Generic NN GEMM: C = (A @ B + bias) * scale
// A: [M,K] row-major (lda), B: [K,N] row-major (ldb), C: [M,N] (ldc)
// klimit!=0: effective K for a block row is min(K, m0+BM)   (causal PV GEMM)
// blockIdx.z batches via byte-element strides aBS/bBS/cBS.
// tf32 WMMA, fp32 accumulate. Requires M%128==0, N%128==0, K%16==0.
// ---------------------------------------------------------------------------
__global__ __launch_bounds__(256) void gemm_nn_tf32(
    const float* __restrict__ A, int lda,
    const float* __restrict__ Bm, int ldb,
    const float* __restrict__ bias,
    float* __restrict__ C, int ldc,
    int M, int N, int K, float scale, int klimit,
    size_t aBS, size_t bBS, size_t cBS)
{
    A  += (size_t)blockIdx.z * aBS;
    Bm += (size_t)blockIdx.z * bBS;
    C  += (size_t)blockIdx.z * cBS;

    __shared__ float As[BM][BK + 8];     // ld 24
    __shared__ float Bs[BK][BN + 8];     // ld 136
    __shared__ float Ep[8][16 * 20];     // per-warp epilogue staging

    const int tid = threadIdx.x;
    const int m0 = blockIdx.y * BM;
    const int n0 = blockIdx.x * BN;
    const int kend = klimit ? min(K, m0 + BM) : K;

    const int warp = tid >> 5, lane = tid & 31;
    const int wm = warp >> 2, wn = warp & 3;   // 2x4 warp grid, 64x32 per warp

    wmma::fragment<wmma::accumulator, 16, 16, 8, float> acc[4][2];
    #pragma unroll
    for (int i = 0; i < 4; i++)
        #pragma unroll
        for (int j = 0; j < 2; j++)
            wmma::fill_fragment(acc[i][j], 0.0f);

    for (int k0 = 0; k0 < kend; k0 += BK) {
        // Stage A tile 128x16 (512 float4, 2 per thread)
        #pragma unroll
        for (int f = tid; f < 512; f += 256) {
            int row = f >> 2;
            int c4  = (f & 3) << 2;
            const float4 v = *reinterpret_cast<const float4*>(
                A + (size_t)(m0 + row) * lda + k0 + c4);
            As[row][c4 + 0] = wmma::__float_to_tf32(v.x);
            As[row][c4 + 1] = wmma::__float_to_tf32(v.y);
            As[row][c4 + 2] = wmma::__float_to_tf32(v.z);
            As[row][c4 + 3] = wmma::__float_to_tf32(v.w);
        }
        // Stage B tile 16x128
        #pragma unroll
        for (int f = tid; f < 512; f += 256) {
            int row = f >> 5;
            int c4  = (f & 31) << 2;
            const float4 v = *reinterpret_cast<const float4*>(
                Bm + (size_t)(k0 + row) * ldb + n0 + c4);
            Bs[row][c4 + 0] = wmma::__float_to_tf32(v.x);
            Bs[row][c4 + 1] = wmma::__float_to_tf32(v.y);
            Bs[row][c4 + 2] = wmma::__float_to_tf32(v.z);
            Bs[row][c4 + 3] = wmma::__float_to_tf32(v.w);
        }
        __syncthreads();

        wmma::fragment<wmma::matrix_a, 16, 16, 8, wmma::precision::tf32, wmma::row_major> af[4];
        wmma::fragment<wmma::matrix_b, 16, 16, 8, wmma::precision::tf32, wmma::row_major> bf[2];
        #pragma unroll
        for (int ks = 0; ks < BK; ks += 8) {
            #pragma unroll
            for (int i = 0; i < 4; i++)
                wmma::load_matrix_sync(af[i], &As[wm * 64 + i * 16][ks], BK + 8);
            #pragma unroll
            for (int j = 0; j < 2; j++)
                wmma::load_matrix_sync(bf[j], &Bs[ks][wn * 32 + j * 16], BN + 8);
            #pragma unroll
            for (int i = 0; i < 4; i++)
                #pragma unroll
                for (int j = 0; j < 2; j++)
                    wmma::mma_sync(acc[i][j], af[i], bf[j], acc[i][j]);
        }
        __syncthreads();
    }

    // Epilogue: per-warp stage through shared so we know (row,col) per element
    float* ep = Ep[warp];
    const int er = lane >> 1;
    const int cb = (lane & 1) << 3;
    #pragma unroll
    for (int i = 0; i < 4; i++) {
        #pragma unroll
        for (int j = 0; j < 2; j++) {
            wmma::store_matrix_sync(ep, acc[i][j], 20, wmma::mem_row_major);
            __syncwarp();
            const int gr  = m0 + wm * 64 + i * 16 + er;
            const int gc0 = n0 + wn * 32 + j * 16 + cb;
            #pragma unroll
            for (int c = 0; c < 8; c++) {
                float v = ep[er * 20 + cb + c];
                if (bias) v += bias[gc0 + c];
                C[(size_t)gr * ldc + gc0 + c] = v * scale;
            }
            __syncwarp();
        }
    }
}

// ---------------------------------------------------------------------------
// TN GEMM with causal mask: scores[b] = Q[b] @ K[b]^T,  masked to NEGV above
// the diagonal. Skips tiles entirely above the diagonal.
// Q,K: [S,D] row-major per batch, scores: [S,S].
// ---------------------------------------------------------------------------
__global__ __launch_bounds__(256) void gemm_tn_causal_tf32(
    const float* __restrict__ Qm,
    const float* __restrict__ Km,
    float* __restrict__ C,
    size_t aBS, size_t bBS, size_t cBS)
{
    const int m0 = blockIdx.y * BM;
    const int n0 = blockIdx.x * BN;
    if (n0 >= m0 + BM) return;   // entire tile above diagonal: never read

    Qm += (size_t)blockIdx.z * aBS;
    Km += (size_t)blockIdx.z * bBS;
    C  += (size_t)blockIdx.z * cBS;

    __shared__ float As[BM][BK + 8];     // Q tile, ld 24
    __shared__ float Bt[BN][BK + 8];     // K tile [n][k], ld 24
    __shared__ float Ep[8][16 * 20];

    const int tid = threadIdx.x;
    const int warp = tid >> 5, lane = tid & 31;
    const int wm = warp >> 2, wn = warp & 3;

    wmma::fragment<wmma::accumulator, 16, 16, 8, float> acc[4][2];
    #pragma unroll
    for (int i = 0; i < 4; i++)
        #pragma unroll
        for (int j = 0; j < 2; j++)
            wmma::fill_fragment(acc[i][j], 0.0f);

    for (int k0 = 0; k0 < Dd; k0 += BK) {
        #pragma unroll
        for (int f = tid; f < 512; f += 256) {
            int row = f >> 2;
            int c4  = (f & 3) << 2;
            const float4 v = *reinterpret_cast<const float4*>(
                Qm + (size_t)(m0 + row) * Dd + k0 + c4);
            As[row][c4 + 0] = wmma::__float_to_tf32(v.x);
            As[row][c4 + 1] = wmma::__float_to_tf32(v.y);
            As[row][c4 + 2] = wmma::__float_to_tf32(v.z);
            As[row][c4 + 3] = wmma::__float_to_tf32(v.w);
        }
        #pragma unroll
        for (int f = tid; f < 512; f += 256) {
            int row = f >> 2;
            int c4  = (f & 3) << 2;
            const float4 v = *reinterpret_cast<const float4*>(
                Km + (size_t)(n0 + row) * Dd + k0 + c4);
            Bt[row][c4 + 0] = wmma::__float_to_tf32(v.x);
            Bt[row][c4 + 1] = wmma::__float_to_tf32(v.y);
            Bt[row][c4 + 2] = wmma::__float_to_tf32(v.z);
            Bt[row][c4 + 3] = wmma::__float_to_tf32(v.w);
        }
        __syncthreads();

        wmma::fragment<wmma::matrix_a, 16, 16, 8, wmma::precision::tf32, wmma::row_major> af[4];
        wmma::fragment<wmma::matrix_b, 16, 16, 8, wmma::precision::tf32, wmma::col_major> bf[2];
        #pragma unroll
        for (int ks = 0; ks < BK; ks += 8) {
            #pragma unroll
            for (int i = 0; i < 4; i++)
                wmma::load_matrix_sync(af[i], &As[wm * 64 + i * 16][ks], BK + 8);
            #pragma unroll
            for (int j = 0; j < 2; j++)
                wmma::load_matrix_sync(bf[j], &Bt[wn * 32 + j * 16][ks], BK + 8);
            #pragma unroll
            for (int i = 0; i < 4; i++)
                #pragma unroll
                for (int j = 0; j < 2; j++)
                    wmma::mma_sync(acc[i][j], af[i], bf[j], acc[i][j]);
        }
        __syncthreads();
    }

    float* ep = Ep[warp];
    const int er = lane >> 1;
    const int cb = (lane & 1) << 3;
    #pragma unroll
    for (int i = 0; i < 4; i++) {
        #pragma unroll
        for (int j = 0; j < 2; j++) {
            wmma::store_matrix_sync(ep, acc[i][j], 20, wmma::mem_row_major);
            __syncwarp();
            const int gr  = m0 + wm * 64 + i * 16 + er;
            const int gc0 = n0 + wn * 32 + j * 16 + cb;
            #pragma unroll
            for (int c = 0; c < 8; c++) {
                const int gc = gc0 + c;
                float v = ep[er * 20 + cb + c];
                C[(size_t)gr * Ss + gc] = (gc <= gr) ? v : NEGV;
            }
            __syncwarp();
        }
    }
}

// ---------------------------------------------------------------------------
// Causal row softmax, in place. One block per (row, batch). Only reads cols
// [0, r]; writes probs there and zeros in (r, diag-block-end) so the
// k-limited PV GEMM reads valid zeros.
// ---------------------------------------------------------------------------
__global__ __launch_bounds__(256) void softmax_causal(float* __restrict__ P)
{
    const int r = blockIdx.x;
    const int b = blockIdx.y;
    float* row = P + ((size_t)b * Ss + r) * Ss;
    const int tid = threadIdx.x;

    float vals[8];
    float mx = -3.0e38f;
    #pragma unroll
    for (int j = 0; j < 8; j++) {
        const int i = tid + j * 256;
        vals[j] = (i <= r) ? row[i] : -3.0e38f;
        mx = fmaxf(mx, vals[j]);
    }

    __shared__ float sd[256];
    sd[tid] = mx;
    __syncthreads();
    for (int s = 128; s > 0; s >>= 1) {
        if (tid < s) sd[tid] = fmaxf(sd[tid], sd[tid + s]);
        __syncthreads();
    }
    mx = sd[0];
    __syncthreads();

    float e[8];
    float sum = 0.0f;
    #pragma unroll
    for (int j = 0; j < 8; j++) {
        const int i = tid + j * 256;
        e[j] = (i <= r) ? __expf(vals[j] - mx) : 0.0f;
        sum += e[j];
    }
    sd[tid] = sum;
    __syncthreads();
    for (int s = 128; s > 0; s >>= 1) {
        if (tid < s) sd[tid] += sd[tid + s];
        __syncthreads();
    }
    const float inv = 1.0f / sd[0];

    const int zlim = (r | 127) + 1;   // end of diagonal 128-block
    #pragma unroll
    for (int j = 0; j < 8; j++) {
        const int i = tid + j * 256;
        if (i <= r)          row[i] = e[j] * inv;
        else if (i < zlim)   row[i] = 0.0f;
    }
}

// ---------------------------------------------------------------------------
// Launch: 3 proj GEMMs -> causal QK^T -> softmax -> k-limited PV GEMM
// ---------------------------------------------------------------------------
extern "C" void kernel_launch(void* const* d_in, const int* in_sizes, int n_in,
                              void* d_out, int out_size)
{
    const float* x  = (const float*)d_in[0];
    // d_in[1] = mask (bool, always causal for this problem) -- unused
    const float* Wq = (const float*)d_in[2];
    const float* bq = (const float*)d_in[3];
    const float* Wk = (const float*)d_in[4];
    const float* bk = (const float*)d_in[5];
    const float* Wv = (const float*)d_in[6];
    const float* bv = (const float*)d_in[7];
    float* out = (float*)d_out;

    void *pQ, *pK, *pV, *pP;
    cudaGetSymbolAddress(&pQ, g_Q);
    cudaGetSymbolAddress(&pK, g_K);
    cudaGetSymbolAddress(&pV, g_V);
    cudaGetSymbolAddress(&pP, g_P);
    float* Q  = (float*)pQ;
    float* Km = (float*)pK;
    float* V  = (float*)pV;
    float* P  = (float*)pP;

    const dim3 blk(256);

    // QKV projections: [16384,1024] @ [1024,1024]
    const dim3 gp(Dd / BN, (Bb * Ss) / BM, 1);
    // q = (x@Wq + bq) / sqrt(D): fold 1/32 into epilogue scale
    gemm_nn_tf32<<<gp, blk>>>(x, Dd, Wq, Dd, bq, Q,  Dd, Bb * Ss, Dd, Dd,
                              0.03125f, 0, 0, 0, 0);
    gemm_nn_tf32<<<gp, blk>>>(x, Dd, Wk, Dd, bk, Km, Dd, Bb * Ss, Dd, Dd,
                              1.0f, 0, 0, 0, 0);
    gemm_nn_tf32<<<gp, blk>>>(x, Dd, Wv, Dd, bv, V,  Dd, Bb * Ss, Dd, Dd,
                              1.0f, 0, 0, 0, 0);

    // scores[b] = Q[b] @ K[b]^T with causal mask
    const dim3 gs(Ss / BN, Ss / BM, Bb);
    gemm_tn_causal_tf32<<<gs, blk>>>(Q, Km, P,
                                     (size_t)Ss * Dd, (size_t)Ss * Dd,
                                     (size_t)Ss * Ss);

    // softmax in place
    const dim3 gm(Ss, Bb);
    softmax_causal<<<gm, blk>>>(P);

    // out[b] = P[b] @ V[b], skipping zero K-blocks past the diagonal
    const dim3 gv(Dd / BN, Ss / BM, Bb);
    gemm_nn_tf32<<<gv, blk>>>(P, Ss, V, Dd, nullptr, out, Dd, Ss, Dd, Ss,
                              1.0f, 1,
                              (size_t)Ss * Ss, (size_t)Ss * Dd,
                              (size_t)Ss * Dd);
}

// round 3
// speedup vs baseline: 1.0124x; 1.0124x over previous
#include <cuda_runtime.h>
#include <cstdint>
#include <mma.h>
#include <math.h>

using namespace nvcuda;

// Problem constants (fixed by reference setup_inputs)
#define Bb 8
#define Ss 2048
#define Dd 1024

// GEMM tiling
#define BM 128
#define BN 128
#define BK 16
#define LDS_A   24                 // BK + 8 pad  (96 B row, 16B aligned)
#define LDS_BN  136                // BN + 8 pad  (544 B row, 16B aligned)
#define A_STAGE (BM * LDS_A)       // 3072 floats
#define B_STAGE_T (BN * LDS_A)     // 3072 floats (TRANSB layout)
#define STAGE_MAX (A_STAGE + B_STAGE_T)   // 6144 floats -> 2 stages = 48 KB

// Scratch: __device__ globals (no runtime allocation allowed)
__device__ float g_Q[(size_t)Bb * Ss * Dd];   // 64 MB
__device__ float g_K[(size_t)Bb * Ss * Dd];   // 64 MB
__device__ float g_V[(size_t)Bb * Ss * Dd];   // 64 MB
__device__ float g_P[(size_t)Bb * Ss * Ss];   // 128 MB (scores -> probs in place)

// ---------------------------------------------------------------------------
// cp.async helpers
// ---------------------------------------------------------------------------
__device__ __forceinline__ void cp16(float* s, const float* g) {
    unsigned int sa = (unsigned int)__cvta_generic_to_shared(s);
    asm volatile("cp.async.cg.shared.global [%0], [%1], 16;" :: "r"(sa), "l"(g));
}
__device__ __forceinline__ void cp_commit() {
    asm volatile("cp.async.commit_group;");
}
template<int N>
__device__ __forceinline__ void cp_wait() {
    asm volatile("cp.async.wait_group %0;" :: "n"(N));
}

// ---------------------------------------------------------------------------
// Pipelined tf32 WMMA GEMM.
//   TRANSB=0: C = (A[M,K] @ B[K,N] + bias) * scale         (proj / PV)
//   TRANSB=1: C = A[M,K] @ B[N,K]^T                        (QK^T)
//   CAUSAL=1: skip tiles fully above diagonal; store only gc <= gr
//   klimit:   effective K per block-row = min(K, m0+BM)     (causal PV)
//   blockIdx.z batches via element strides aBS/bBS/cBS.
// Requires M%128==0, N%128==0, K%16==0. 256 threads, 8 warps of 64x32.
// ---------------------------------------------------------------------------
template<bool TRANSB, bool CAUSAL>
__global__ __launch_bounds__(256) void gemm_k(
    const float* __restrict__ A, int lda, size_t aBS,
    const float* __restrict__ B, int ldb, size_t bBS,
    const float* __restrict__ bias,
    float* __restrict__ C, int ldc, size_t cBS,
    int K, float scale, int klimit)
{
    const int m0 = blockIdx.y * BM;
    const int n0 = blockIdx.x * BN;
    if (CAUSAL && n0 >= m0 + BM) return;   // tile entirely above diagonal

    A += (size_t)blockIdx.z * aBS;
    B += (size_t)blockIdx.z * bBS;
    C += (size_t)blockIdx.z * cBS;

    __shared__ __align__(16) float smem[2][STAGE_MAX];

    const int tid  = threadIdx.x;
    const int warp = tid >> 5, lane = tid & 31;
    const int wm = warp >> 2, wn = warp & 3;       // 2x4 warp grid, 64x32/warp

    const int kend   = klimit ? min(K, m0 + BM) : K;
    const int ktiles = kend / BK;

    auto load_stage = [&](int s, int k0) {
        float* As = smem[s];
        float* Bs = smem[s] + A_STAGE;
        // A tile: 128 x 16 floats = 512 float4
        #pragma unroll
        for (int f = tid; f < 512; f += 256) {
            int row = f >> 2, c4 = (f & 3) << 2;
            cp16(&As[row * LDS_A + c4], A + (size_t)(m0 + row) * lda + k0 + c4);
        }
        if (TRANSB) {
            // B tile: 128 rows (n) x 16 floats (k)
            #pragma unroll
            for (int f = tid; f < 512; f += 256) {
                int row = f >> 2, c4 = (f & 3) << 2;
                cp16(&Bs[row * LDS_A + c4], B + (size_t)(n0 + row) * ldb + k0 + c4);
            }
        } else {
            // B tile: 16 rows (k) x 128 floats (n)
            #pragma unroll
            for (int f = tid; f < 512; f += 256) {
                int row = f >> 5, c4 = (f & 31) << 2;
                cp16(&Bs[row * LDS_BN + c4], B + (size_t)(k0 + row) * ldb + n0 + c4);
            }
        }
    };

    wmma::fragment<wmma::accumulator, 16, 16, 8, float> acc[4][2];
    #pragma unroll
    for (int i = 0; i < 4; i++)
        #pragma unroll
        for (int j = 0; j < 2; j++)
            wmma::fill_fragment(acc[i][j], 0.0f);

    load_stage(0, 0);
    cp_commit();

    for (int kt = 0; kt < ktiles; kt++) {
        if (kt + 1 < ktiles) {
            load_stage((kt + 1) & 1, (kt + 1) * BK);
            cp_commit();
            cp_wait<1>();
        } else {
            cp_wait<0>();
        }
        __syncthreads();

        const float* As = smem[kt & 1];
        const float* Bs = smem[kt & 1] + A_STAGE;

        #pragma unroll
        for (int ks = 0; ks < BK; ks += 8) {
            wmma::fragment<wmma::matrix_a, 16, 16, 8, wmma::precision::tf32,
                           wmma::row_major> af[4];
            #pragma unroll
            for (int i = 0; i < 4; i++) {
                wmma::load_matrix_sync(af[i], &As[(wm * 64 + i * 16) * LDS_A + ks], LDS_A);
                #pragma unroll
                for (int t = 0; t < af[i].num_elements; t++)
                    af[i].x[t] = wmma::__float_to_tf32(af[i].x[t]);
            }
            if constexpr (TRANSB) {
                wmma::fragment<wmma::matrix_b, 16, 16, 8, wmma::precision::tf32,
                               wmma::col_major> bf[2];
                #pragma unroll
                for (int j = 0; j < 2; j++) {
                    wmma::load_matrix_sync(bf[j], &Bs[(wn * 32 + j * 16) * LDS_A + ks], LDS_A);
                    #pragma unroll
                    for (int t = 0; t < bf[j].num_elements; t++)
                        bf[j].x[t] = wmma::__float_to_tf32(bf[j].x[t]);
                }
                #pragma unroll
                for (int i = 0; i < 4; i++)
                    #pragma unroll
                    for (int j = 0; j < 2; j++)
                        wmma::mma_sync(acc[i][j], af[i], bf[j], acc[i][j]);
            } else {
                wmma::fragment<wmma::matrix_b, 16, 16, 8, wmma::precision::tf32,
                               wmma::row_major> bf[2];
                #pragma unroll
                for (int j = 0; j < 2; j++) {
                    wmma::load_matrix_sync(bf[j], &Bs[ks * LDS_BN + wn * 32 + j * 16], LDS_BN);
                    #pragma unroll
                    for (int t = 0; t < bf[j].num_elements; t++)
                        bf[j].x[t] = wmma::__float_to_tf32(bf[j].x[t]);
                }
                #pragma unroll
                for (int i = 0; i < 4; i++)
                    #pragma unroll
                    for (int j = 0; j < 2; j++)
                        wmma::mma_sync(acc[i][j], af[i], bf[j], acc[i][j]);
            }
        }
        __syncthreads();
    }

    // Epilogue: per-warp staging through smem (aliases stage 0; all smem
    // reads completed at the loop's final __syncthreads).
    float* ep = smem[0] + warp * 320;           // 16 rows x ld 20
    const int er = lane >> 1;
    const int cb = (lane & 1) << 3;
    #pragma unroll
    for (int i = 0; i < 4; i++) {
        #pragma unroll
        for (int j = 0; j < 2; j++) {
            wmma::store_matrix_sync(ep, acc[i][j], 20, wmma::mem_row_major);
            __syncwarp();
            const int gr  = m0 + wm * 64 + i * 16 + er;
            const int gc0 = n0 + wn * 32 + j * 16 + cb;
            #pragma unroll
            for (int c = 0; c < 8; c++) {
                const int gc = gc0 + c;
                float v = ep[er * 20 + cb + c];
                if (bias) v += bias[gc];
                v *= scale;
                // CAUSAL: above-diagonal entries are never read by softmax
                // (it substitutes -3e38 for i > r), so skip those stores.
                if (!CAUSAL || gc <= gr)
                    C[(size_t)gr * ldc + gc] = v;
            }
            __syncwarp();
        }
    }
}

// ---------------------------------------------------------------------------
// Causal row softmax, in place. One block per (row, batch). Reads only cols
// [0, r]; writes probs there and zeros in (r, diag-block-end) so the
// k-limited PV GEMM reads valid zeros.
// ---------------------------------------------------------------------------
__global__ __launch_bounds__(256) void softmax_causal(float* __restrict__ P)
{
    const int r = blockIdx.x;
    const int b = blockIdx.y;
    float* row = P + ((size_t)b * Ss + r) * Ss;
    const int tid = threadIdx.x;

    float vals[8];
    float mx = -3.0e38f;
    #pragma unroll
    for (int j = 0; j < 8; j++) {
        const int i = tid + j * 256;
        vals[j] = (i <= r) ? row[i] : -3.0e38f;
        mx = fmaxf(mx, vals[j]);
    }

    __shared__ float sd[256];
    sd[tid] = mx;
    __syncthreads();
    for (int s = 128; s > 0; s >>= 1) {
        if (tid < s) sd[tid] = fmaxf(sd[tid], sd[tid + s]);
        __syncthreads();
    }
    mx = sd[0];
    __syncthreads();

    float e[8];
    float sum = 0.0f;
    #pragma unroll
    for (int j = 0; j < 8; j++) {
        const int i = tid + j * 256;
        e[j] = (i <= r) ? __expf(vals[j] - mx) : 0.0f;
        sum += e[j];
    }
    sd[tid] = sum;
    __syncthreads();
    for (int s = 128; s > 0; s >>= 1) {
        if (tid < s) sd[tid] += sd[tid + s];
        __syncthreads();
    }
    const float inv = 1.0f / sd[0];

    const int zlim = (r | 127) + 1;   // end of the diagonal 128-block
    #pragma unroll
    for (int j = 0; j < 8; j++) {
        const int i = tid + j * 256;
        if (i <= r)          row[i] = e[j] * inv;
        else if (i < zlim)   row[i] = 0.0f;
    }
}

// ---------------------------------------------------------------------------
// Launch: 3 proj GEMMs -> causal QK^T -> softmax -> k-limited PV GEMM
// ---------------------------------------------------------------------------
extern "C" void kernel_launch(void* const* d_in, const int* in_sizes, int n_in,
                              void* d_out, int out_size)
{
    const float* x  = (const float*)d_in[0];
    // d_in[1] = mask (bool, always causal for this problem) -- unused
    const float* Wq = (const float*)d_in[2];
    const float* bq = (const float*)d_in[3];
    const float* Wk = (const float*)d_in[4];
    const float* bk = (const float*)d_in[5];
    const float* Wv = (const float*)d_in[6];
    const float* bv = (const float*)d_in[7];
    float* out = (float*)d_out;

    void *pQ, *pK, *pV, *pP;
    cudaGetSymbolAddress(&pQ, g_Q);
    cudaGetSymbolAddress(&pK, g_K);
    cudaGetSymbolAddress(&pV, g_V);
    cudaGetSymbolAddress(&pP, g_P);
    float* Q  = (float*)pQ;
    float* Km = (float*)pK;
    float* V  = (float*)pV;
    float* P  = (float*)pP;

    const dim3 blk(256);

    // QKV projections: [16384,1024] @ [1024,1024]  (+bias, q scaled by 1/32)
    const dim3 gp(Dd / BN, (Bb * Ss) / BM, 1);
    gemm_k<false, false><<<gp, blk>>>(x, Dd, 0, Wq, Dd, 0, bq,
                                      Q,  Dd, 0, Dd, 0.03125f, 0);
    gemm_k<false, false><<<gp, blk>>>(x, Dd, 0, Wk, Dd, 0, bk,
                                      Km, Dd, 0, Dd, 1.0f, 0);
    gemm_k<false, false><<<gp, blk>>>(x, Dd, 0, Wv, Dd, 0, bv,
                                      V,  Dd, 0, Dd, 1.0f, 0);

    // scores[b] = Q[b] @ K[b]^T, lower-triangle tiles only
    const dim3 gs(Ss / BN, Ss / BM, Bb);
    gemm_k<true, true><<<gs, blk>>>(Q, Dd, (size_t)Ss * Dd,
                                    Km, Dd, (size_t)Ss * Dd, nullptr,
                                    P, Ss, (size_t)Ss * Ss, Dd, 1.0f, 0);

    // softmax in place
    const dim3 gm(Ss, Bb);
    softmax_causal<<<gm, blk>>>(P);

    // out[b] = P[b] @ V[b], skipping zero K-blocks past the diagonal
    const dim3 gv(Dd / BN, Ss / BM, Bb);
    gemm_k<false, false><<<gv, blk>>>(P, Ss, (size_t)Ss * Ss,
                                      V, Dd, (size_t)Ss * Dd, nullptr,
                                      out, Dd, (size_t)Ss * Dd, Ss, 1.0f, 1);
}

// round 6
// speedup vs baseline: 4.7216x; 4.6636x over previous
#include <cuda_runtime.h>
#include <cuda_fp16.h>
#include <cstdint>

// Problem constants (fixed by reference setup_inputs)
#define Bb 8
#define Ss 2048
#define Dd 1024

// GEMM tiling: CTA 128x128, k-chunk 64 halves (128 B rows), 3-stage ring
#define BM 128
#define BN 128
#define BKH 64
#define NST 3
#define TILE_BYTES (128 * 128)          // 16 KB (128 rows x 128 B)
#define STG (2 * TILE_BYTES)            // 32 KB (A + B)
#define SMEM_SZ (NST * STG)             // 96 KB

// Scratch (__device__ globals; no runtime allocation allowed)
__device__ __half g_Xh [(size_t)Bb * Ss * Dd];   // x, fp16            32 MB
__device__ __half g_WTh[(size_t)3 * Dd * Dd];    // Wq/k/v^T, fp16      6 MB
__device__ __half g_Qh [(size_t)Bb * Ss * Dd];   // q/sqrt(D), fp16    32 MB
__device__ __half g_Kh [(size_t)Bb * Ss * Dd];   // k, fp16            32 MB
__device__ __half g_Vh [(size_t)Bb * Ss * Dd];   // v, fp16            32 MB
__device__ __half g_VTh[(size_t)Bb * Ss * Dd];   // v^T per batch      32 MB
__device__ float  g_S  [(size_t)Bb * Ss * Ss];   // logits fp32       128 MB
__device__ __half g_Ph [(size_t)Bb * Ss * Ss];   // probs fp16         64 MB

// ---------------------------------------------------------------------------
// PTX helpers (all sm_80-level; compiles for base sm_100)
// ---------------------------------------------------------------------------
__device__ __forceinline__ unsigned smem_u32(const void* p) {
    return (unsigned)__cvta_generic_to_shared(p);
}
__device__ __forceinline__ void cp16(void* s, const void* g) {
    unsigned sa = smem_u32(s);
    asm volatile("cp.async.cg.shared.global [%0], [%1], 16;" :: "r"(sa), "l"(g));
}
__device__ __forceinline__ void cp_commit() {
    asm volatile("cp.async.commit_group;");
}
template<int N>
__device__ __forceinline__ void cp_wait() {
    asm volatile("cp.async.wait_group %0;" :: "n"(N));
}
#define LDSM4(R, addr) \
    asm volatile("ldmatrix.sync.aligned.m8n8.x4.shared.b16 {%0,%1,%2,%3}, [%4];" \
        : "=r"((R)[0]), "=r"((R)[1]), "=r"((R)[2]), "=r"((R)[3]) : "r"(addr))

__device__ __forceinline__ void mma16816(float* c, const unsigned* a, const unsigned* b) {
    asm volatile(
        "mma.sync.aligned.m16n8k16.row.col.f32.f16.f16.f32 "
        "{%0,%1,%2,%3}, {%4,%5,%6,%7}, {%8,%9}, {%0,%1,%2,%3};"
        : "+f"(c[0]), "+f"(c[1]), "+f"(c[2]), "+f"(c[3])
        : "r"(a[0]), "r"(a[1]), "r"(a[2]), "r"(a[3]), "r"(b[0]), "r"(b[1]));
}

// ---------------------------------------------------------------------------
// fp16 GEMM:  C[M,N] = (A[M,K] @ B[N,K]^T + bias) * scale
//   OUTF32: C fp32 (else fp16)
//   CAUSAL: skip tiles above diagonal; predicate stores on diagonal tiles
//   KLIM:   effective K = m0 + BM (causal PV)
//   BIAS:   add fp32 bias[col] before scale
// 256 threads, 8 warps (2x4), warp tile 64x32. Tiles: 128 rows x 128B,
// XOR-16B swizzle, loaded by cp.async; fragments via ldmatrix.x4.
// ---------------------------------------------------------------------------
template<bool OUTF32, bool CAUSAL, bool KLIM, bool BIAS>
__global__ __launch_bounds__(256) void hgemm(
    const __half* __restrict__ A, int lda, size_t aBS,
    const __half* __restrict__ B, int ldb, size_t bBS,
    const float* __restrict__ bias,
    void* __restrict__ Cv, int ldc, size_t cBS,
    int K, float scale)
{
    const int m0 = blockIdx.y * BM;
    const int n0 = blockIdx.x * BN;
    if (CAUSAL && n0 >= m0 + BM) return;

    A += (size_t)blockIdx.z * aBS;
    B += (size_t)blockIdx.z * bBS;

    extern __shared__ char smem[];
    const int tid = threadIdx.x, warp = tid >> 5, lane = tid & 31;
    const int wm = warp >> 2, wn = warp & 3;     // 2x4 grid, 64x32 per warp

    const int kend = KLIM ? (m0 + BM) : K;
    const int nkt  = kend / BKH;

    auto load_stage = [&](int kt) {
        char* base = smem + (kt % NST) * STG;
        const int kh = kt * BKH;                 // halves
        #pragma unroll
        for (int t = 0; t < 4; t++) {            // A: 1024 16B chunks
            int idx = tid + (t << 8);
            int row = idx >> 3, c = idx & 7;
            int cc = c ^ (row & 7);
            cp16(base + row * 128 + cc * 16,
                 (const char*)(A + (size_t)(m0 + row) * lda + kh) + c * 16);
        }
        #pragma unroll
        for (int t = 0; t < 4; t++) {            // B: 1024 16B chunks
            int idx = tid + (t << 8);
            int row = idx >> 3, c = idx & 7;
            int cc = c ^ (row & 7);
            cp16(base + TILE_BYTES + row * 128 + cc * 16,
                 (const char*)(B + (size_t)(n0 + row) * ldb + kh) + c * 16);
        }
    };

    float acc[4][4][4];
    #pragma unroll
    for (int i = 0; i < 4; i++)
        #pragma unroll
        for (int j = 0; j < 4; j++)
            #pragma unroll
            for (int e = 0; e < 4; e++) acc[i][j][e] = 0.0f;

    load_stage(0); cp_commit();
    if (nkt > 1) load_stage(1);
    cp_commit();

    for (int kt = 0; kt < nkt; kt++) {
        cp_wait<1>();
        __syncthreads();
        if (kt + 2 < nkt) load_stage(kt + 2);
        cp_commit();

        const unsigned aw = smem_u32(smem + (kt % NST) * STG);
        const unsigned bw = aw + TILE_BYTES;

        #pragma unroll
        for (int s = 0; s < 4; s++) {            // 4 x k16 per 64-half chunk
            unsigned af[4][4], bf[2][4];
            #pragma unroll
            for (int i = 0; i < 4; i++) {
                int row = wm * 64 + i * 16 + (lane & 15);
                int cc  = (s * 2 + (lane >> 4)) ^ (row & 7);
                LDSM4(af[i], aw + row * 128 + cc * 16);
            }
            #pragma unroll
            for (int j = 0; j < 2; j++) {
                int n  = wn * 32 + j * 16 + (lane & 7) + ((lane >> 4) << 3);
                int cc = (s * 2 + ((lane >> 3) & 1)) ^ (n & 7);
                LDSM4(bf[j], bw + n * 128 + cc * 16);
            }
            #pragma unroll
            for (int i = 0; i < 4; i++)
                #pragma unroll
                for (int j = 0; j < 2; j++) {
                    mma16816(acc[i][2 * j + 0], af[i], &bf[j][0]);
                    mma16816(acc[i][2 * j + 1], af[i], &bf[j][2]);
                }
        }
    }

    // ---------------- epilogue (direct from registers) ----------------
    // c frag: c0,c1 -> row lane/4, cols 2(lane%4)+{0,1}; c2,c3 -> row+8
    const bool diag = CAUSAL && (n0 + BN > m0);  // only diagonal tile predicated
    #pragma unroll
    for (int i = 0; i < 4; i++) {
        const int rbase = m0 + wm * 64 + i * 16 + (lane >> 2);
        #pragma unroll
        for (int h = 0; h < 2; h++) {
            const int gr = rbase + h * 8;
            #pragma unroll
            for (int nf = 0; nf < 4; nf++) {
                const int gc = n0 + wn * 32 + nf * 8 + (lane & 3) * 2;
                float v0 = acc[i][nf][2 * h + 0];
                float v1 = acc[i][nf][2 * h + 1];
                if (BIAS) { v0 += bias[gc]; v1 += bias[gc + 1]; }
                v0 *= scale; v1 *= scale;
                if (OUTF32) {
                    float* C = (float*)Cv + (size_t)blockIdx.z * cBS;
                    if (!diag) {
                        *reinterpret_cast<float2*>(C + (size_t)gr * ldc + gc) =
                            make_float2(v0, v1);
                    } else {
                        if (gc     <= gr) C[(size_t)gr * ldc + gc]     = v0;
                        if (gc + 1 <= gr) C[(size_t)gr * ldc + gc + 1] = v1;
                    }
                } else {
                    __half* C = (__half*)Cv + (size_t)blockIdx.z * cBS;
                    *reinterpret_cast<__half2*>(C + (size_t)gr * ldc + gc) =
                        __floats2half2_rn(v0, v1);
                }
            }
        }
    }
}

// ---------------------------------------------------------------------------
// Conversion / transpose passes
// ---------------------------------------------------------------------------
__global__ __launch_bounds__(256) void conv_x(const float4* __restrict__ in,
                                              uint2* __restrict__ out) {
    size_t i = (size_t)blockIdx.x * 256 + threadIdx.x;
    float4 v = in[i];
    __half2 h0 = __floats2half2_rn(v.x, v.y);
    __half2 h1 = __floats2half2_rn(v.z, v.w);
    uint2 o;
    o.x = *reinterpret_cast<unsigned*>(&h0);
    o.y = *reinterpret_cast<unsigned*>(&h1);
    out[i] = o;
}

// W [K=in][N=out] fp32 -> WT [N][K] fp16
__global__ __launch_bounds__(256) void transpose_w(const float* __restrict__ W,
                                                   __half* __restrict__ WT) {
    __shared__ float t[32][33];
    const int n0 = blockIdx.x * 32, k0 = blockIdx.y * 32;
    const int tx = threadIdx.x & 31, ty = threadIdx.x >> 5;   // 32 x 8
    #pragma unroll
    for (int r = ty; r < 32; r += 8)
        t[r][tx] = W[(size_t)(k0 + r) * Dd + n0 + tx];
    __syncthreads();
    #pragma unroll
    for (int r = ty; r < 32; r += 8)
        WT[(size_t)(n0 + r) * Dd + k0 + tx] = __float2half_rn(t[tx][r]);
}

// V [b][s][d] fp16 -> VT [b][d][s] fp16
__global__ __launch_bounds__(256) void transpose_v(const __half* __restrict__ V,
                                                   __half* __restrict__ VT) {
    __shared__ __half t[32][33];
    const __half* Vb = V  + (size_t)blockIdx.z * Ss * Dd;
    __half* Tb       = VT + (size_t)blockIdx.z * Ss * Dd;
    const int d0 = blockIdx.x * 32, s0 = blockIdx.y * 32;
    const int tx = threadIdx.x & 31, ty = threadIdx.x >> 5;
    #pragma unroll
    for (int r = ty; r < 32; r += 8)
        t[r][tx] = Vb[(size_t)(s0 + r) * Dd + d0 + tx];
    __syncthreads();
    #pragma unroll
    for (int r = ty; r < 32; r += 8)
        Tb[(size_t)(d0 + r) * Ss + s0 + tx] = t[tx][r];
}

// ---------------------------------------------------------------------------
// Causal row softmax: read fp32 logits, write fp16 probs; zero-fill
// (r, diag-block-end) so the k-limited PV GEMM reads valid zeros.
// ---------------------------------------------------------------------------
__global__ __launch_bounds__(256) void softmax_causal(const float* __restrict__ S,
                                                      __half* __restrict__ P)
{
    const int r = blockIdx.x;
    const int b = blockIdx.y;
    const float* row = S + ((size_t)b * Ss + r) * Ss;
    __half* prow     = P + ((size_t)b * Ss + r) * Ss;
    const int tid = threadIdx.x;

    float vals[8];
    float mx = -3.0e38f;
    #pragma unroll
    for (int j = 0; j < 8; j++) {
        const int i = tid + j * 256;
        vals[j] = (i <= r) ? row[i] : -3.0e38f;
        mx = fmaxf(mx, vals[j]);
    }

    __shared__ float sd[256];
    sd[tid] = mx;
    __syncthreads();
    for (int s = 128; s > 0; s >>= 1) {
        if (tid < s) sd[tid] = fmaxf(sd[tid], sd[tid + s]);
        __syncthreads();
    }
    mx = sd[0];
    __syncthreads();

    float e[8];
    float sum = 0.0f;
    #pragma unroll
    for (int j = 0; j < 8; j++) {
        const int i = tid + j * 256;
        e[j] = (i <= r) ? __expf(vals[j] - mx) : 0.0f;
        sum += e[j];
    }
    sd[tid] = sum;
    __syncthreads();
    for (int s = 128; s > 0; s >>= 1) {
        if (tid < s) sd[tid] += sd[tid + s];
        __syncthreads();
    }
    const float inv = 1.0f / sd[0];

    const int zlim = (r | 127) + 1;      // == PV k-limit for this row's block
    #pragma unroll
    for (int j = 0; j < 8; j++) {
        const int i = tid + j * 256;
        if (i <= r)          prow[i] = __float2half_rn(e[j] * inv);
        else if (i < zlim)   prow[i] = __ushort_as_half((unsigned short)0);
    }
}

// ---------------------------------------------------------------------------
// Launch
// ---------------------------------------------------------------------------
extern "C" void kernel_launch(void* const* d_in, const int* in_sizes, int n_in,
                              void* d_out, int out_size)
{
    const float* x  = (const float*)d_in[0];
    // d_in[1] = mask (always causal) -- unused
    const float* Wq = (const float*)d_in[2];
    const float* bq = (const float*)d_in[3];
    const float* Wk = (const float*)d_in[4];
    const float* bk = (const float*)d_in[5];
    const float* Wv = (const float*)d_in[6];
    const float* bv = (const float*)d_in[7];
    float* out = (float*)d_out;

    void *pXh, *pWTh, *pQh, *pKh, *pVh, *pVTh, *pS, *pPh;
    cudaGetSymbolAddress(&pXh,  g_Xh);
    cudaGetSymbolAddress(&pWTh, g_WTh);
    cudaGetSymbolAddress(&pQh,  g_Qh);
    cudaGetSymbolAddress(&pKh,  g_Kh);
    cudaGetSymbolAddress(&pVh,  g_Vh);
    cudaGetSymbolAddress(&pVTh, g_VTh);
    cudaGetSymbolAddress(&pS,   g_S);
    cudaGetSymbolAddress(&pPh,  g_Ph);
    __half* Xh  = (__half*)pXh;
    __half* WTh = (__half*)pWTh;
    __half* Qh  = (__half*)pQh;
    __half* Kh  = (__half*)pKh;
    __half* Vh  = (__half*)pVh;
    __half* VTh = (__half*)pVTh;
    float*  S   = (float*)pS;
    __half* Ph  = (__half*)pPh;

    cudaFuncSetAttribute(hgemm<false, false, false, true>,
                         cudaFuncAttributeMaxDynamicSharedMemorySize, SMEM_SZ);
    cudaFuncSetAttribute(hgemm<true, true, false, false>,
                         cudaFuncAttributeMaxDynamicSharedMemorySize, SMEM_SZ);
    cudaFuncSetAttribute(hgemm<true, false, true, false>,
                         cudaFuncAttributeMaxDynamicSharedMemorySize, SMEM_SZ);

    // 1. Convert inputs / weights to fp16 (weights transposed)
    conv_x<<<(Bb * Ss * Dd) / (256 * 4), 256>>>((const float4*)x, (uint2*)Xh);
    const dim3 tg(Dd / 32, Dd / 32);
    transpose_w<<<tg, 256>>>(Wq, WTh);
    transpose_w<<<tg, 256>>>(Wk, WTh + (size_t)Dd * Dd);
    transpose_w<<<tg, 256>>>(Wv, WTh + (size_t)2 * Dd * Dd);

    // 2. Projections: X[16384,1024] @ WT^T (+bias); q pre-scaled by 1/32
    const dim3 gp(Dd / BN, (Bb * Ss) / BM, 1);
    hgemm<false, false, false, true><<<gp, 256, SMEM_SZ>>>(
        Xh, Dd, 0, WTh, Dd, 0, bq, Qh, Dd, 0, Dd, 0.03125f);
    hgemm<false, false, false, true><<<gp, 256, SMEM_SZ>>>(
        Xh, Dd, 0, WTh + (size_t)Dd * Dd, Dd, 0, bk, Kh, Dd, 0, Dd, 1.0f);
    hgemm<false, false, false, true><<<gp, 256, SMEM_SZ>>>(
        Xh, Dd, 0, WTh + (size_t)2 * Dd * Dd, Dd, 0, bv, Vh, Dd, 0, Dd, 1.0f);

    // 3. V^T per batch
    transpose_v<<<dim3(Dd / 32, Ss / 32, Bb), 256>>>(Vh, VTh);

    // 4. logits[b] = Q[b] @ K[b]^T (fp32, causal tiles only)
    const dim3 gs(Ss / BN, Ss / BM, Bb);
    hgemm<true, true, false, false><<<gs, 256, SMEM_SZ>>>(
        Qh, Dd, (size_t)Ss * Dd, Kh, Dd, (size_t)Ss * Dd, nullptr,
        S, Ss, (size_t)Ss * Ss, Dd, 1.0f);

    // 5. softmax -> fp16 probs
    softmax_causal<<<dim3(Ss, Bb), 256>>>(S, Ph);

    // 6. out[b] = P[b] @ (V^T[b])^T, K limited to the diagonal block end
    const dim3 gv(Dd / BN, Ss / BM, Bb);
    hgemm<true, false, true, false><<<gv, 256, SMEM_SZ>>>(
        Ph, Ss, (size_t)Ss * Ss, VTh, Ss, (size_t)Ss * Dd, nullptr,
        out, Dd, (size_t)Ss * Dd, Ss, 1.0f);
}